// round 10
// baseline (speedup 1.0000x reference)
#include <cuda_runtime.h>
#include <cuda_fp16.h>
#include <cstdint>

// Problem constants
#define BB 16
#define SS 1024
#define HH 4
#define QDIM 128
#define KDIM 256
#define VDIM 256
#define CH   1024          // H*KD = H*VD
#define MROWS (BB*SS)      // 16384

// ---------------------------------------------------------------------------
// Device scratch (no allocation allowed)
// ---------------------------------------------------------------------------
__device__ __align__(256) float g_TV[MROWS*CH];            // 64 MB fp32 V projection
__device__ __align__(256) float g_colsum4[BB*HH*4*SS];
__device__ __align__(256) float g_meanv[BB*CH];
__device__ __align__(256) float g_WoW1[CH*128];
__device__ __align__(256) float g_bvec[128];

__device__ __align__(256) __half g_Xqh[MROWS*QDIM], g_Xql[MROWS*QDIM];
__device__ __align__(256) __half g_Xkh[MROWS*KDIM], g_Xkl[MROWS*KDIM];
__device__ __align__(256) __half g_Xvh[MROWS*VDIM], g_Xvl[MROWS*VDIM];
__device__ __align__(256) __half g_Wqth[CH*QDIM], g_Wqtl[CH*QDIM];
__device__ __align__(256) __half g_Wkth[CH*KDIM], g_Wktl[CH*KDIM];
__device__ __align__(256) __half g_Wvth[CH*VDIM], g_Wvtl[CH*VDIM];
__device__ __align__(256) __half g_TQh[MROWS*CH];                       // hi only (Ql term dropped)
__device__ __align__(256) __half g_TKh[MROWS*CH], g_TKl[MROWS*CH];

// ---------------------------------------------------------------------------
// Low-level helpers (sm_80-era PTX; valid on plain sm_103 target)
// ---------------------------------------------------------------------------
__device__ __forceinline__ uint32_t smem_u32(const void* p) {
    uint32_t a;
    asm("{ .reg .u64 t; cvta.to.shared.u64 t, %1; cvt.u32.u64 %0, t; }"
        : "=r"(a) : "l"(p));
    return a;
}
__device__ __forceinline__ void cp16(uint32_t dst, const void* src) {
    asm volatile("cp.async.cg.shared.global [%0], [%1], 16;"
                 :: "r"(dst), "l"(__cvta_generic_to_global(src)));
}
__device__ __forceinline__ void ldmx4(uint32_t* r, uint32_t addr) {
    asm volatile("ldmatrix.sync.aligned.m8n8.x4.shared.b16 {%0,%1,%2,%3}, [%4];"
                 : "=r"(r[0]), "=r"(r[1]), "=r"(r[2]), "=r"(r[3]) : "r"(addr));
}
__device__ __forceinline__ void mma_f16(float* c, const uint32_t* a, const uint32_t* b) {
    asm volatile("mma.sync.aligned.m16n8k16.row.col.f32.f16.f16.f32 "
                 "{%0,%1,%2,%3}, {%4,%5,%6,%7}, {%8,%9}, {%0,%1,%2,%3};"
                 : "+f"(c[0]), "+f"(c[1]), "+f"(c[2]), "+f"(c[3])
                 : "r"(a[0]), "r"(a[1]), "r"(a[2]), "r"(a[3]), "r"(b[0]), "r"(b[1]));
}

// ---------------------------------------------------------------------------
// Split fp32 -> fp16 hi + fp16 lo (elementwise, vectorized by 4)
// ---------------------------------------------------------------------------
__global__ void __launch_bounds__(256) split_kernel(
    const float* __restrict__ x, __half* __restrict__ h,
    __half* __restrict__ l, int n4)
{
    int i = blockIdx.x * blockDim.x + threadIdx.x;
    if (i >= n4) return;
    float4 v = reinterpret_cast<const float4*>(x)[i];
    float a[4] = {v.x, v.y, v.z, v.w};
    __half hh[4], ll[4];
#pragma unroll
    for (int j = 0; j < 4; j++) {
        hh[j] = __float2half(a[j]);
        ll[j] = __float2half(a[j] - __half2float(hh[j]));
    }
    reinterpret_cast<__half2*>(h)[i * 2 + 0] = __halves2half2(hh[0], hh[1]);
    reinterpret_cast<__half2*>(h)[i * 2 + 1] = __halves2half2(hh[2], hh[3]);
    reinterpret_cast<__half2*>(l)[i * 2 + 0] = __halves2half2(ll[0], ll[1]);
    reinterpret_cast<__half2*>(l)[i * 2 + 1] = __halves2half2(ll[2], ll[3]);
}

// Transpose + split: W[K,N] -> Wt hi/lo [N,K]
__global__ void __launch_bounds__(256) tsplit_kernel(
    const float* __restrict__ W, __half* __restrict__ th,
    __half* __restrict__ tl, int K, int N)
{
    __shared__ float tile[32][33];
    int tx = threadIdx.x, ty = threadIdx.y;
    int n0 = blockIdx.x * 32, k0 = blockIdx.y * 32;
#pragma unroll
    for (int i = 0; i < 4; i++) {
        int k = k0 + ty + i * 8;
        tile[ty + i * 8][tx] = W[(size_t)k * N + n0 + tx];
    }
    __syncthreads();
#pragma unroll
    for (int i = 0; i < 4; i++) {
        int n = n0 + ty + i * 8;
        int k = k0 + tx;
        float v = tile[tx][ty + i * 8];
        __half h = __float2half(v);
        __half l = __float2half(v - __half2float(h));
        th[(size_t)n * K + k] = h;
        tl[(size_t)n * K + k] = l;
    }
}

// ---------------------------------------------------------------------------
// mma.sync split-fp16 NT GEMM:  C[m,n] = sum_k A[m,k]*B[n,k]
// TERMS==3: D = Ah.Bh + Ah.Bl + Al.Bh   (full split, ~2^-22 error)
// TERMS==2: D = Ah.Bh + Ah.Bl           (A hi only, ~2^-11 error)
// BM=128, BN=128, BK=32, 256 thr (8 warps 2x4, warp tile 64x32).
// 3-stage cp.async circular pipeline, ONE __syncthreads per K-chunk:
//   wait(stage c) -> sync -> issue stage c+2 -> compute stage c.
// Buffer (c+2)%3 == (c-1)%3 was last read before the sync -> safe.
// SMEM slot order: ((row>>3)*4 + kc)*128 + (row&7)*16 (conflict-free).
// mode 0: fp32 out via __stcs (+bias); mode 1: fp16 hi(/lo) out (+bias).
// ---------------------------------------------------------------------------
#define OFF_AL 8192
#define OFF_BH 16384
#define OFF_BL 24576
#define STG    32768
#define NSTAGE 3
#define SMEM_TOTAL (NSTAGE*STG)   // 96 KB

template<int TERMS>
__global__ void __launch_bounds__(256, 2) mma_nt(
    const __half* __restrict__ Ah, const __half* __restrict__ Al,
    const __half* __restrict__ Bh, const __half* __restrict__ Bl,
    int K, int lda, int ldb,
    long long strideZ, long long strideCz,
    const float* __restrict__ bias, int mode,
    float* __restrict__ Cf, __half* __restrict__ Chi, __half* __restrict__ Clo)
{
    extern __shared__ __align__(1024) char smem[];
    uint32_t sb = smem_u32(smem);
    int t = threadIdx.x;
    int lane = t & 31, warp = t >> 5;
    int wm = warp >> 2, wn = warp & 3;              // 2 x 4 warp grid, warp tile 64x32
    int m0 = blockIdx.y * 128, n0 = blockIdx.x * 128;
    size_t zo = (size_t)blockIdx.z * (size_t)strideZ;

    // cp.async mapping: row r (0..127), two 16B chunks kc2, kc2+1
    int r = t & 127, kc2 = (t >> 7) * 2;
    uint32_t so = (uint32_t)(((r >> 3) * 4 + kc2) * 128 + (r & 7) * 16);
    const __half* pAh = Ah + zo + (size_t)(m0 + r) * lda + kc2 * 8;
    const __half* pAl = (TERMS == 3) ? (Al + zo + (size_t)(m0 + r) * lda + kc2 * 8) : nullptr;
    const __half* pBh = Bh + zo + (size_t)(n0 + r) * ldb + kc2 * 8;
    const __half* pBl = Bl + zo + (size_t)(n0 + r) * ldb + kc2 * 8;

    int nch = K >> 5;

    // prologue: stages 0 and 1
#pragma unroll
    for (int pc = 0; pc < 2; pc++) {
        int kt = pc << 5;
        uint32_t s1 = sb + pc * STG;
        cp16(s1 + so,                  pAh + kt);
        cp16(s1 + so + 128,            pAh + kt + 8);
        if (TERMS == 3) {
            cp16(s1 + OFF_AL + so,       pAl + kt);
            cp16(s1 + OFF_AL + so + 128, pAl + kt + 8);
        }
        cp16(s1 + OFF_BH + so,         pBh + kt);
        cp16(s1 + OFF_BH + so + 128,   pBh + kt + 8);
        cp16(s1 + OFF_BL + so,         pBl + kt);
        cp16(s1 + OFF_BL + so + 128,   pBl + kt + 8);
        asm volatile("cp.async.commit_group;");
    }

    float acc[4][4][4];
#pragma unroll
    for (int i = 0; i < 4; i++)
#pragma unroll
        for (int j = 0; j < 4; j++)
#pragma unroll
            for (int q = 0; q < 4; q++) acc[i][j][q] = 0.f;

    int stage = 0;
    for (int c = 0; c < nch; c++) {
        if (c == nch - 1) asm volatile("cp.async.wait_group 0;");
        else              asm volatile("cp.async.wait_group 1;");
        __syncthreads();

        if (c + 2 < nch) {
            int kt = (c + 2) << 5;
            int nst = stage + 2; if (nst >= NSTAGE) nst -= NSTAGE;
            uint32_t s1 = sb + nst * STG;
            cp16(s1 + so,                  pAh + kt);
            cp16(s1 + so + 128,            pAh + kt + 8);
            if (TERMS == 3) {
                cp16(s1 + OFF_AL + so,       pAl + kt);
                cp16(s1 + OFF_AL + so + 128, pAl + kt + 8);
            }
            cp16(s1 + OFF_BH + so,         pBh + kt);
            cp16(s1 + OFF_BH + so + 128,   pBh + kt + 8);
            cp16(s1 + OFF_BL + so,         pBl + kt);
            cp16(s1 + OFF_BL + so + 128,   pBl + kt + 8);
            asm volatile("cp.async.commit_group;");
        }

        uint32_t bs = sb + stage * STG;
#pragma unroll
        for (int s = 0; s < 2; s++) {               // two k16 steps per chunk
            uint32_t af[4][4], bf[4][2], blf[4][2];
            int akcl = s * 2 + (lane >> 4);
            int arl  = (lane >> 3) & 1;
            int lr   = (lane & 7) * 16;
#pragma unroll
            for (int mt = 0; mt < 4; mt++) {
                int rb = wm * 8 + mt * 2 + arl;
                ldmx4(af[mt], bs + (uint32_t)((rb * 4 + akcl) * 128) + lr);
            }
            int bkcl = s * 2 + ((lane >> 3) & 1);
#pragma unroll
            for (int p = 0; p < 2; p++) {
                int rb = wn * 4 + p * 2 + (lane >> 4);
                uint32_t addr = bs + OFF_BH + (uint32_t)((rb * 4 + bkcl) * 128) + lr;
                uint32_t rr[4], rl[4];
                ldmx4(rr, addr);
                ldmx4(rl, addr + (OFF_BL - OFF_BH));
                bf[p*2][0]  = rr[0]; bf[p*2][1]  = rr[1];
                bf[p*2+1][0] = rr[2]; bf[p*2+1][1] = rr[3];
                blf[p*2][0]  = rl[0]; blf[p*2][1]  = rl[1];
                blf[p*2+1][0] = rl[2]; blf[p*2+1][1] = rl[3];
            }
#pragma unroll
            for (int mt = 0; mt < 4; mt++)
#pragma unroll
                for (int nt = 0; nt < 4; nt++) {
                    mma_f16(acc[mt][nt], af[mt], bf[nt]);
                    mma_f16(acc[mt][nt], af[mt], blf[nt]);
                }
            if (TERMS == 3) {
                // reload af registers with A-lo fragments (register reuse)
#pragma unroll
                for (int mt = 0; mt < 4; mt++) {
                    int rb = wm * 8 + mt * 2 + arl;
                    ldmx4(af[mt], bs + OFF_AL + (uint32_t)((rb * 4 + akcl) * 128) + lr);
                }
#pragma unroll
                for (int mt = 0; mt < 4; mt++)
#pragma unroll
                    for (int nt = 0; nt < 4; nt++)
                        mma_f16(acc[mt][nt], af[mt], bf[nt]);
            }
        }
        if (++stage >= NSTAGE) stage = 0;
    }

    // epilogue: registers -> gmem (ldc = 1024)
    size_t cz = (size_t)blockIdx.z * (size_t)strideCz;
#pragma unroll
    for (int mt = 0; mt < 4; mt++)
#pragma unroll
        for (int nt = 0; nt < 4; nt++) {
            int row = m0 + wm * 64 + mt * 16 + (lane >> 2);
            int col = n0 + wn * 32 + nt * 8 + (lane & 3) * 2;
            float b0 = bias ? bias[col] : 0.f;
            float b1 = bias ? bias[col + 1] : 0.f;
            float v0 = acc[mt][nt][0] + b0, v1 = acc[mt][nt][1] + b1;
            float v2 = acc[mt][nt][2] + b0, v3 = acc[mt][nt][3] + b1;
            size_t o0 = (size_t)row * 1024 + col;
            size_t o1 = (size_t)(row + 8) * 1024 + col;
            if (mode == 0) {
                __stcs(reinterpret_cast<float2*>(Cf + cz + o0), make_float2(v0, v1));
                __stcs(reinterpret_cast<float2*>(Cf + cz + o1), make_float2(v2, v3));
            } else {
                __half h0 = __float2half(v0), h1 = __float2half(v1);
                __half h2 = __float2half(v2), h3 = __float2half(v3);
                *reinterpret_cast<__half2*>(Chi + o0) = __halves2half2(h0, h1);
                *reinterpret_cast<__half2*>(Chi + o1) = __halves2half2(h2, h3);
                if (Clo) {
                    *reinterpret_cast<__half2*>(Clo + o0) = __halves2half2(
                        __float2half(v0 - __half2float(h0)), __float2half(v1 - __half2float(h1)));
                    *reinterpret_cast<__half2*>(Clo + o1) = __halves2half2(
                        __float2half(v2 - __half2float(h2)), __float2half(v3 - __half2float(h3)));
                }
            }
        }
}

// ---------------------------------------------------------------------------
// SIMT GEMM kept for the small WoW1 ([1024,2048]@[2048,128])
// ---------------------------------------------------------------------------
__global__ void __launch_bounds__(256) gemm_nn_bias(
    const float* __restrict__ A, const float* __restrict__ B,
    const float* __restrict__ bias, float* __restrict__ C,
    int M, int N, int K)
{
    const int BM = 128, BN = 64, BK = 16;
    __shared__ float As[BK][BM];
    __shared__ float Bs[BK][BN];
    int tid = threadIdx.x;
    int tx = tid & 15, ty = tid >> 4;
    int m0 = blockIdx.y * BM, n0 = blockIdx.x * BN;
    float acc[8][4];
#pragma unroll
    for (int i = 0; i < 8; i++)
#pragma unroll
        for (int j = 0; j < 4; j++) acc[i][j] = 0.f;
    int arow = tid >> 2, acol = (tid & 3) * 4;
    int brow = tid >> 4, bcol = (tid & 15) * 4;
    for (int kt = 0; kt < K; kt += BK) {
#pragma unroll
        for (int p = 0; p < 2; p++) {
            int rr = arow + p * 64;
            float4 v = *reinterpret_cast<const float4*>(&A[(size_t)(m0 + rr) * K + kt + acol]);
            As[acol + 0][rr] = v.x; As[acol + 1][rr] = v.y;
            As[acol + 2][rr] = v.z; As[acol + 3][rr] = v.w;
        }
        {
            float4 v = *reinterpret_cast<const float4*>(&B[(size_t)(kt + brow) * N + n0 + bcol]);
            *reinterpret_cast<float4*>(&Bs[brow][bcol]) = v;
        }
        __syncthreads();
#pragma unroll
        for (int kk = 0; kk < BK; kk++) {
            float a[8], b[4];
#pragma unroll
            for (int i = 0; i < 8; i++) a[i] = As[kk][ty * 8 + i];
#pragma unroll
            for (int j = 0; j < 4; j++) b[j] = Bs[kk][tx * 4 + j];
#pragma unroll
            for (int i = 0; i < 8; i++)
#pragma unroll
                for (int j = 0; j < 4; j++) acc[i][j] = fmaf(a[i], b[j], acc[i][j]);
        }
        __syncthreads();
    }
    float bb[4] = {0.f, 0.f, 0.f, 0.f};
    if (bias) {
#pragma unroll
        for (int j = 0; j < 4; j++) bb[j] = bias[n0 + tx * 4 + j];
    }
#pragma unroll
    for (int i = 0; i < 8; i++) {
        int m = m0 + ty * 8 + i;
        float4 v;
        v.x = acc[i][0] + bb[0]; v.y = acc[i][1] + bb[1];
        v.z = acc[i][2] + bb[2]; v.w = acc[i][3] + bb[3];
        *reinterpret_cast<float4*>(&C[(size_t)m * N + n0 + tx * 4]) = v;
    }
}

// ---------------------------------------------------------------------------
// In-place softmax over attn rows + stratified column sums (r = s mod 4).
// Grid 2048: blk = (bh[6] | r[2] | chunk[3]); each warp owns 4 rows.
// ---------------------------------------------------------------------------
__global__ void __launch_bounds__(256) softmax_colsum(
    float* __restrict__ attn, float* __restrict__ colsum)
{
    int blk = blockIdx.x;              // 0..2047
    int bh = blk >> 5;                 // 0..63
    int r  = (blk >> 3) & 3;
    int chunk = blk & 7;
    float* base = attn + (size_t)bh * (SS * SS);
    int warp = threadIdx.x >> 5, lane = threadIdx.x & 31;
    float cs[32];
#pragma unroll
    for (int i = 0; i < 32; i++) cs[i] = 0.f;

#pragma unroll
    for (int j4 = 0; j4 < 4; j4++) {
        int i = chunk * 32 + warp * 4 + j4;     // 0..255 within stratum
        int s = r + 4 * i;
        float* row = base + (size_t)s * SS;
        float4 v[8];
#pragma unroll
        for (int j = 0; j < 8; j++)
            v[j] = *reinterpret_cast<float4*>(&row[lane * 4 + 128 * j]);
        float mx = -1e30f;
#pragma unroll
        for (int j = 0; j < 8; j++)
            mx = fmaxf(mx, fmaxf(fmaxf(v[j].x, v[j].y), fmaxf(v[j].z, v[j].w)));
#pragma unroll
        for (int o = 16; o > 0; o >>= 1)
            mx = fmaxf(mx, __shfl_xor_sync(0xffffffffu, mx, o));
        float sum = 0.f;
#pragma unroll
        for (int j = 0; j < 8; j++) {
            v[j].x = __expf(v[j].x - mx); v[j].y = __expf(v[j].y - mx);
            v[j].z = __expf(v[j].z - mx); v[j].w = __expf(v[j].w - mx);
            sum += v[j].x + v[j].y + v[j].z + v[j].w;
        }
#pragma unroll
        for (int o = 16; o > 0; o >>= 1)
            sum += __shfl_xor_sync(0xffffffffu, sum, o);
        float inv = 1.0f / sum;
#pragma unroll
        for (int j = 0; j < 8; j++) {
            v[j].x *= inv; v[j].y *= inv; v[j].z *= inv; v[j].w *= inv;
            cs[4 * j + 0] += v[j].x; cs[4 * j + 1] += v[j].y;
            cs[4 * j + 2] += v[j].z; cs[4 * j + 3] += v[j].w;
            *reinterpret_cast<float4*>(&row[lane * 4 + 128 * j]) = v[j];
        }
    }
    float* cbase = colsum + (size_t)(bh * 4 + r) * SS;
#pragma unroll
    for (int j = 0; j < 8; j++)
#pragma unroll
        for (int q = 0; q < 4; q++)
            atomicAdd(&cbase[lane * 4 + 128 * j + q], cs[4 * j + q]);
}

__global__ void init_zero()
{
    int i = blockIdx.x * blockDim.x + threadIdx.x;
    if (i < BB * HH * 4 * SS) g_colsum4[i] = 0.f;
    if (i < BB * CH) g_meanv[i] = 0.f;
}

__global__ void __launch_bounds__(256) meanvec_kernel()
{
    int b = blockIdx.x, kc = blockIdx.y, d = threadIdx.x;
    float acc0 = 0.f, acc1 = 0.f, acc2 = 0.f, acc3 = 0.f;
    for (int h = 0; h < HH; h++) {
        const float* tv = g_TV + ((size_t)b << 20) + ((size_t)h << 18);
        const float* cs = g_colsum4 + (size_t)(b * 4 + h) * 4 * SS;
        int k0 = kc * 256;
        for (int k = k0; k < k0 + 256; k++) {
            float tvv = tv[(size_t)k * 256 + d];
            acc0 = fmaf(cs[k],          tvv, acc0);
            acc1 = fmaf(cs[SS + k],     tvv, acc1);
            acc2 = fmaf(cs[2 * SS + k], tvv, acc2);
            acc3 = fmaf(cs[3 * SS + k], tvv, acc3);
        }
    }
    const float sc = 1.0f / 1024.0f;
    atomicAdd(&g_meanv[b * CH + 0 * 256 + d], acc0 * sc);
    atomicAdd(&g_meanv[b * CH + 1 * 256 + d], acc1 * sc);
    atomicAdd(&g_meanv[b * CH + 2 * 256 + d], acc2 * sc);
    atomicAdd(&g_meanv[b * CH + 3 * 256 + d], acc3 * sc);
}

__global__ void bvec_kernel(const float* __restrict__ bo,
                            const float* __restrict__ W1,
                            const float* __restrict__ b1)
{
    int j = threadIdx.x;
    float acc = b1[j];
    for (int m = 0; m < 2048; m++) acc = fmaf(bo[m], W1[m * 128 + j], acc);
    g_bvec[j] = acc;
}

__global__ void out_final(float* __restrict__ out)
{
    int b = blockIdx.x, j = threadIdx.x;
    float acc = g_bvec[j];
    const float* mv = g_meanv + b * CH;
    for (int c = 0; c < CH; c++)
        acc = fmaf(mv[c], g_WoW1[c * 128 + j], acc);
    out[b * 128 + j] = acc;
}

// ---------------------------------------------------------------------------
extern "C" void kernel_launch(void* const* d_in, const int* in_sizes, int n_in,
                              void* d_out, int out_size)
{
    const float* query = (const float*)d_in[0];
    const float* key   = (const float*)d_in[1];
    const float* value = (const float*)d_in[2];
    const float* Wq    = (const float*)d_in[3];
    const float* bq    = (const float*)d_in[4];
    const float* Wk    = (const float*)d_in[5];
    const float* bk    = (const float*)d_in[6];
    const float* Wv    = (const float*)d_in[7];
    const float* bv    = (const float*)d_in[8];
    const float* Wo    = (const float*)d_in[9];
    const float* bo    = (const float*)d_in[10];
    const float* W1    = (const float*)d_in[11];
    const float* b1    = (const float*)d_in[12];
    (void)in_sizes; (void)n_in; (void)out_size;

    float* out  = (float*)d_out;
    float* attn = out + (size_t)BB * 128;   // tuple layout: [out, attn]

    void* p;
    cudaGetSymbolAddress(&p, g_TV);      float* TV   = (float*)p;
    cudaGetSymbolAddress(&p, g_colsum4); float* CSUM = (float*)p;
    cudaGetSymbolAddress(&p, g_WoW1);    float* WoW1 = (float*)p;
    __half *Xqh, *Xql, *Xkh, *Xkl, *Xvh, *Xvl;
    __half *Wqth, *Wqtl, *Wkth, *Wktl, *Wvth, *Wvtl;
    __half *TQh, *TKh, *TKl;
    cudaGetSymbolAddress(&p, g_Xqh); Xqh = (__half*)p;
    cudaGetSymbolAddress(&p, g_Xql); Xql = (__half*)p;
    cudaGetSymbolAddress(&p, g_Xkh); Xkh = (__half*)p;
    cudaGetSymbolAddress(&p, g_Xkl); Xkl = (__half*)p;
    cudaGetSymbolAddress(&p, g_Xvh); Xvh = (__half*)p;
    cudaGetSymbolAddress(&p, g_Xvl); Xvl = (__half*)p;
    cudaGetSymbolAddress(&p, g_Wqth); Wqth = (__half*)p;
    cudaGetSymbolAddress(&p, g_Wqtl); Wqtl = (__half*)p;
    cudaGetSymbolAddress(&p, g_Wkth); Wkth = (__half*)p;
    cudaGetSymbolAddress(&p, g_Wktl); Wktl = (__half*)p;
    cudaGetSymbolAddress(&p, g_Wvth); Wvth = (__half*)p;
    cudaGetSymbolAddress(&p, g_Wvtl); Wvtl = (__half*)p;
    cudaGetSymbolAddress(&p, g_TQh); TQh = (__half*)p;
    cudaGetSymbolAddress(&p, g_TKh); TKh = (__half*)p;
    cudaGetSymbolAddress(&p, g_TKl); TKl = (__half*)p;

    cudaFuncSetAttribute(mma_nt<3>, cudaFuncAttributeMaxDynamicSharedMemorySize, SMEM_TOTAL);
    cudaFuncSetAttribute(mma_nt<2>, cudaFuncAttributeMaxDynamicSharedMemorySize, SMEM_TOTAL);

    init_zero<<<1024, 256>>>();

    // Split inputs into fp16 hi/lo
    split_kernel<<<(MROWS * QDIM / 4 + 255) / 256, 256>>>(query, Xqh, Xql, MROWS * QDIM / 4);
    split_kernel<<<(MROWS * KDIM / 4 + 255) / 256, 256>>>(key,   Xkh, Xkl, MROWS * KDIM / 4);
    split_kernel<<<(MROWS * VDIM / 4 + 255) / 256, 256>>>(value, Xvh, Xvl, MROWS * VDIM / 4);

    // Transpose + split weights: W[K,1024] -> Wt[1024,K]
    tsplit_kernel<<<dim3(32, QDIM / 32), dim3(32, 8)>>>(Wq, Wqth, Wqtl, QDIM, CH);
    tsplit_kernel<<<dim3(32, KDIM / 32), dim3(32, 8)>>>(Wk, Wkth, Wktl, KDIM, CH);
    tsplit_kernel<<<dim3(32, VDIM / 32), dim3(32, 8)>>>(Wv, Wvth, Wvtl, VDIM, CH);

    // Projections (3-term): [16384, Kin] @ Wt^T -> [16384, 1024]
    dim3 gp(CH / 128, MROWS / 128, 1);
    mma_nt<3><<<gp, 256, SMEM_TOTAL>>>(Xqh, Xql, Wqth, Wqtl, QDIM, QDIM, QDIM,
                                       0, 0, bq, 1, nullptr, TQh, nullptr);   // hi only
    mma_nt<3><<<gp, 256, SMEM_TOTAL>>>(Xkh, Xkl, Wkth, Wktl, KDIM, KDIM, KDIM,
                                       0, 0, bk, 1, nullptr, TKh, TKl);
    mma_nt<3><<<gp, 256, SMEM_TOTAL>>>(Xvh, Xvl, Wvth, Wvtl, VDIM, VDIM, VDIM,
                                       0, 0, bv, 0, TV, nullptr, nullptr);

    // Small fused tail weights
    gemm_nn_bias<<<dim3(2, 8), 256>>>(Wo, W1, nullptr, WoW1, CH, 128, 2048);
    bvec_kernel<<<1, 128>>>(bo, W1, b1);

    // Scores (2-term): per z=(b*4+h), contiguous [1024,256] head block at z*S*KD
    dim3 gs(SS / 128, SS / 128, BB * HH);
    mma_nt<2><<<gs, 256, SMEM_TOTAL>>>(TQh, nullptr, TKh, TKl, KDIM, KDIM, KDIM,
                                       (long long)SS * KDIM, (long long)SS * SS,
                                       nullptr, 0, attn, nullptr, nullptr);

    // Softmax in place + stratified column sums
    softmax_colsum<<<2048, 256>>>(attn, CSUM);

    // Collapse attended-mean and final projections
    meanvec_kernel<<<dim3(BB, 4), 256>>>();
    out_final<<<BB, 128>>>(out);
}

// round 13
// speedup vs baseline: 1.3546x; 1.3546x over previous
#include <cuda_runtime.h>
#include <cuda_fp16.h>
#include <cstdint>

// Problem constants
#define BB 16
#define SS 1024
#define HH 4
#define QDIM 128
#define KDIM 256
#define VDIM 256
#define CH   1024          // H*KD = H*VD
#define MROWS (BB*SS)      // 16384

// ---------------------------------------------------------------------------
// Device scratch (no allocation allowed)
// ---------------------------------------------------------------------------
__device__ __align__(256) float g_TV[MROWS*CH];            // 64 MB fp32 V projection
__device__ __align__(256) float g_colsum4[BB*HH*4*SS];
__device__ __align__(256) float g_meanv[BB*CH];
__device__ __align__(256) float g_WoW1[CH*128];
__device__ __align__(256) float g_bvec[128];

__device__ __align__(256) __half g_Xqh[MROWS*QDIM];
__device__ __align__(256) __half g_Xkh[MROWS*KDIM];
__device__ __align__(256) __half g_Xvh[MROWS*VDIM];
__device__ __align__(256) __half g_Wqth[CH*QDIM], g_Wqtl[CH*QDIM];
__device__ __align__(256) __half g_Wkth[CH*KDIM], g_Wktl[CH*KDIM];
__device__ __align__(256) __half g_Wvth[CH*VDIM], g_Wvtl[CH*VDIM];
__device__ __align__(256) __half g_TQh[MROWS*CH];
__device__ __align__(256) __half g_TKh[MROWS*CH];

// ---------------------------------------------------------------------------
// Low-level helpers (sm_80-era PTX; valid on plain sm_103 target)
// ---------------------------------------------------------------------------
__device__ __forceinline__ uint32_t smem_u32(const void* p) {
    uint32_t a;
    asm("{ .reg .u64 t; cvta.to.shared.u64 t, %1; cvt.u32.u64 %0, t; }"
        : "=r"(a) : "l"(p));
    return a;
}
__device__ __forceinline__ void cp16(uint32_t dst, const void* src) {
    asm volatile("cp.async.cg.shared.global [%0], [%1], 16;"
                 :: "r"(dst), "l"(__cvta_generic_to_global(src)));
}
__device__ __forceinline__ void ldmx4(uint32_t* r, uint32_t addr) {
    asm volatile("ldmatrix.sync.aligned.m8n8.x4.shared.b16 {%0,%1,%2,%3}, [%4];"
                 : "=r"(r[0]), "=r"(r[1]), "=r"(r[2]), "=r"(r[3]) : "r"(addr));
}
__device__ __forceinline__ void mma_f16(float* c, const uint32_t* a, const uint32_t* b) {
    asm volatile("mma.sync.aligned.m16n8k16.row.col.f32.f16.f16.f32 "
                 "{%0,%1,%2,%3}, {%4,%5,%6,%7}, {%8,%9}, {%0,%1,%2,%3};"
                 : "+f"(c[0]), "+f"(c[1]), "+f"(c[2]), "+f"(c[3])
                 : "r"(a[0]), "r"(a[1]), "r"(a[2]), "r"(a[3]), "r"(b[0]), "r"(b[1]));
}

// ---------------------------------------------------------------------------
// Convert fp32 -> fp16 (hi only, vectorized by 4)
// ---------------------------------------------------------------------------
__global__ void __launch_bounds__(256) convert_kernel(
    const float* __restrict__ x, __half* __restrict__ h, int n4)
{
    int i = blockIdx.x * blockDim.x + threadIdx.x;
    if (i >= n4) return;
    float4 v = reinterpret_cast<const float4*>(x)[i];
    reinterpret_cast<__half2*>(h)[i * 2 + 0] =
        __halves2half2(__float2half(v.x), __float2half(v.y));
    reinterpret_cast<__half2*>(h)[i * 2 + 1] =
        __halves2half2(__float2half(v.z), __float2half(v.w));
}

// Transpose + split: W[K,N] -> Wt hi/lo [N,K]
__global__ void __launch_bounds__(256) tsplit_kernel(
    const float* __restrict__ W, __half* __restrict__ th,
    __half* __restrict__ tl, int K, int N)
{
    __shared__ float tile[32][33];
    int tx = threadIdx.x, ty = threadIdx.y;
    int n0 = blockIdx.x * 32, k0 = blockIdx.y * 32;
#pragma unroll
    for (int i = 0; i < 4; i++) {
        int k = k0 + ty + i * 8;
        tile[ty + i * 8][tx] = W[(size_t)k * N + n0 + tx];
    }
    __syncthreads();
#pragma unroll
    for (int i = 0; i < 4; i++) {
        int n = n0 + ty + i * 8;
        int k = k0 + tx;
        float v = tile[tx][ty + i * 8];
        __half h = __float2half(v);
        __half l = __float2half(v - __half2float(h));
        th[(size_t)n * K + k] = h;
        tl[(size_t)n * K + k] = l;
    }
}

// ---------------------------------------------------------------------------
// mma.sync split-fp16 NT GEMM:  C[m,n] = sum_k A[m,k]*B[n,k]
// TERMS==2: D = Ah.Bh + Ah.Bl   (B split; A hi only)
// TERMS==1: D = Ah.Bh           (pure fp16)
// BM=128, BN=128, BK=32, 256 thr (8 warps 2x4, warp tile 64x32), 2-stage
// cp.async (known-good R9 pipeline). SMEM slot order:
// ((row>>3)*4 + kc)*128 + (row&7)*16 -> conflict-free stores + ldmatrix.
// ldc fixed 1024. mode 0: fp32 out (+bias); mode 1: fp16 hi out (+bias).
// ---------------------------------------------------------------------------
#define OFF_BH 8192
#define OFF_BL 16384
#define STG    24576
#define SMEM_TOTAL (2*STG)   // 48 KB

template<int TERMS>
__global__ void __launch_bounds__(256, 2) mma_nt(
    const __half* __restrict__ Ah,
    const __half* __restrict__ Bh, const __half* __restrict__ Bl,
    int K, int lda, int ldb,
    long long strideZ, long long strideCz,
    const float* __restrict__ bias, int mode,
    float* __restrict__ Cf, __half* __restrict__ Chi)
{
    extern __shared__ __align__(1024) char smem[];
    uint32_t sb = smem_u32(smem);
    int t = threadIdx.x;
    int lane = t & 31, warp = t >> 5;
    int wm = warp >> 2, wn = warp & 3;              // 2 x 4 warp grid, warp tile 64x32
    int m0 = blockIdx.y * 128, n0 = blockIdx.x * 128;
    size_t zo = (size_t)blockIdx.z * (size_t)strideZ;

    // cp.async mapping: row r (0..127), two 16B chunks kc2, kc2+1
    int r = t & 127, kc2 = (t >> 7) * 2;
    uint32_t so = (uint32_t)(((r >> 3) * 4 + kc2) * 128 + (r & 7) * 16);
    const __half* pAh = Ah + zo + (size_t)(m0 + r) * lda + kc2 * 8;
    const __half* pBh = Bh + zo + (size_t)(n0 + r) * ldb + kc2 * 8;
    const __half* pBl = (TERMS >= 2) ? (Bl + zo + (size_t)(n0 + r) * ldb + kc2 * 8) : nullptr;

    int nch = K >> 5;

    // prologue: chunk 0 -> stage 0
    cp16(sb + so,                  pAh);
    cp16(sb + so + 128,            pAh + 8);
    cp16(sb + OFF_BH + so,         pBh);
    cp16(sb + OFF_BH + so + 128,   pBh + 8);
    if (TERMS >= 2) {
        cp16(sb + OFF_BL + so,       pBl);
        cp16(sb + OFF_BL + so + 128, pBl + 8);
    }
    asm volatile("cp.async.commit_group;");

    float acc[4][4][4];
#pragma unroll
    for (int i = 0; i < 4; i++)
#pragma unroll
        for (int j = 0; j < 4; j++)
#pragma unroll
            for (int q = 0; q < 4; q++) acc[i][j][q] = 0.f;

    for (int c = 0; c < nch; c++) {
        if (c + 1 < nch) {
            int kt = (c + 1) << 5;
            uint32_t s1 = sb + ((c + 1) & 1) * STG;
            cp16(s1 + so,                  pAh + kt);
            cp16(s1 + so + 128,            pAh + kt + 8);
            cp16(s1 + OFF_BH + so,         pBh + kt);
            cp16(s1 + OFF_BH + so + 128,   pBh + kt + 8);
            if (TERMS >= 2) {
                cp16(s1 + OFF_BL + so,       pBl + kt);
                cp16(s1 + OFF_BL + so + 128, pBl + kt + 8);
            }
            asm volatile("cp.async.commit_group;");
            asm volatile("cp.async.wait_group 1;");
        } else {
            asm volatile("cp.async.wait_group 0;");
        }
        __syncthreads();

        uint32_t bs = sb + (c & 1) * STG;
#pragma unroll
        for (int s = 0; s < 2; s++) {               // two k16 steps per chunk
            uint32_t af[4][4], bf[4][2], blf[4][2];
            int akcl = s * 2 + (lane >> 4);
            int arl  = (lane >> 3) & 1;
            int lr   = (lane & 7) * 16;
#pragma unroll
            for (int mt = 0; mt < 4; mt++) {
                int rb = wm * 8 + mt * 2 + arl;
                ldmx4(af[mt], bs + (uint32_t)((rb * 4 + akcl) * 128) + lr);
            }
            int bkcl = s * 2 + ((lane >> 3) & 1);
#pragma unroll
            for (int p = 0; p < 2; p++) {
                int rb = wn * 4 + p * 2 + (lane >> 4);
                uint32_t addr = bs + OFF_BH + (uint32_t)((rb * 4 + bkcl) * 128) + lr;
                uint32_t rr[4];
                ldmx4(rr, addr);
                bf[p*2][0]  = rr[0]; bf[p*2][1]  = rr[1];
                bf[p*2+1][0] = rr[2]; bf[p*2+1][1] = rr[3];
                if (TERMS >= 2) {
                    uint32_t rl[4];
                    ldmx4(rl, addr + (OFF_BL - OFF_BH));
                    blf[p*2][0]  = rl[0]; blf[p*2][1]  = rl[1];
                    blf[p*2+1][0] = rl[2]; blf[p*2+1][1] = rl[3];
                }
            }
#pragma unroll
            for (int mt = 0; mt < 4; mt++)
#pragma unroll
                for (int nt = 0; nt < 4; nt++) {
                    mma_f16(acc[mt][nt], af[mt], bf[nt]);
                    if (TERMS >= 2) mma_f16(acc[mt][nt], af[mt], blf[nt]);
                }
        }
        __syncthreads();
    }

    // epilogue: registers -> gmem (ldc = 1024)
    size_t cz = (size_t)blockIdx.z * (size_t)strideCz;
#pragma unroll
    for (int mt = 0; mt < 4; mt++)
#pragma unroll
        for (int nt = 0; nt < 4; nt++) {
            int row = m0 + wm * 64 + mt * 16 + (lane >> 2);
            int col = n0 + wn * 32 + nt * 8 + (lane & 3) * 2;
            float b0 = bias ? bias[col] : 0.f;
            float b1 = bias ? bias[col + 1] : 0.f;
            float v0 = acc[mt][nt][0] + b0, v1 = acc[mt][nt][1] + b1;
            float v2 = acc[mt][nt][2] + b0, v3 = acc[mt][nt][3] + b1;
            size_t o0 = (size_t)row * 1024 + col;
            size_t o1 = (size_t)(row + 8) * 1024 + col;
            if (mode == 0) {
                *reinterpret_cast<float2*>(Cf + cz + o0) = make_float2(v0, v1);
                *reinterpret_cast<float2*>(Cf + cz + o1) = make_float2(v2, v3);
            } else {
                *reinterpret_cast<__half2*>(Chi + o0) =
                    __halves2half2(__float2half(v0), __float2half(v1));
                *reinterpret_cast<__half2*>(Chi + o1) =
                    __halves2half2(__float2half(v2), __float2half(v3));
            }
        }
}

// ---------------------------------------------------------------------------
// SIMT GEMM kept for the small WoW1 ([1024,2048]@[2048,128])
// ---------------------------------------------------------------------------
__global__ void __launch_bounds__(256) gemm_nn_bias(
    const float* __restrict__ A, const float* __restrict__ B,
    const float* __restrict__ bias, float* __restrict__ C,
    int M, int N, int K)
{
    const int BM = 128, BN = 64, BK = 16;
    __shared__ float As[BK][BM];
    __shared__ float Bs[BK][BN];
    int tid = threadIdx.x;
    int tx = tid & 15, ty = tid >> 4;
    int m0 = blockIdx.y * BM, n0 = blockIdx.x * BN;
    float acc[8][4];
#pragma unroll
    for (int i = 0; i < 8; i++)
#pragma unroll
        for (int j = 0; j < 4; j++) acc[i][j] = 0.f;
    int arow = tid >> 2, acol = (tid & 3) * 4;
    int brow = tid >> 4, bcol = (tid & 15) * 4;
    for (int kt = 0; kt < K; kt += BK) {
#pragma unroll
        for (int p = 0; p < 2; p++) {
            int rr = arow + p * 64;
            float4 v = *reinterpret_cast<const float4*>(&A[(size_t)(m0 + rr) * K + kt + acol]);
            As[acol + 0][rr] = v.x; As[acol + 1][rr] = v.y;
            As[acol + 2][rr] = v.z; As[acol + 3][rr] = v.w;
        }
        {
            float4 v = *reinterpret_cast<const float4*>(&B[(size_t)(kt + brow) * N + n0 + bcol]);
            *reinterpret_cast<float4*>(&Bs[brow][bcol]) = v;
        }
        __syncthreads();
#pragma unroll
        for (int kk = 0; kk < BK; kk++) {
            float a[8], b[4];
#pragma unroll
            for (int i = 0; i < 8; i++) a[i] = As[kk][ty * 8 + i];
#pragma unroll
            for (int j = 0; j < 4; j++) b[j] = Bs[kk][tx * 4 + j];
#pragma unroll
            for (int i = 0; i < 8; i++)
#pragma unroll
                for (int j = 0; j < 4; j++) acc[i][j] = fmaf(a[i], b[j], acc[i][j]);
        }
        __syncthreads();
    }
    float bb[4] = {0.f, 0.f, 0.f, 0.f};
    if (bias) {
#pragma unroll
        for (int j = 0; j < 4; j++) bb[j] = bias[n0 + tx * 4 + j];
    }
#pragma unroll
    for (int i = 0; i < 8; i++) {
        int m = m0 + ty * 8 + i;
        float4 v;
        v.x = acc[i][0] + bb[0]; v.y = acc[i][1] + bb[1];
        v.z = acc[i][2] + bb[2]; v.w = acc[i][3] + bb[3];
        *reinterpret_cast<float4*>(&C[(size_t)m * N + n0 + tx * 4]) = v;
    }
}

// ---------------------------------------------------------------------------
// In-place softmax over attn rows + stratified column sums (r = s mod 4)
// ---------------------------------------------------------------------------
__global__ void __launch_bounds__(256) softmax_colsum(
    float* __restrict__ attn, float* __restrict__ colsum)
{
    int blk = blockIdx.x;
    int r = blk & 3;
    int bh = blk >> 2;
    float* base = attn + (size_t)bh * (SS * SS);
    int warp = threadIdx.x >> 5, lane = threadIdx.x & 31;
    float cs[32];
#pragma unroll
    for (int i = 0; i < 32; i++) cs[i] = 0.f;

    for (int i = warp; i < 256; i += 8) {
        int s = r + 4 * i;
        float* row = base + (size_t)s * SS;
        float4 v[8];
#pragma unroll
        for (int j = 0; j < 8; j++)
            v[j] = *reinterpret_cast<float4*>(&row[lane * 4 + 128 * j]);
        float mx = -1e30f;
#pragma unroll
        for (int j = 0; j < 8; j++)
            mx = fmaxf(mx, fmaxf(fmaxf(v[j].x, v[j].y), fmaxf(v[j].z, v[j].w)));
#pragma unroll
        for (int o = 16; o > 0; o >>= 1)
            mx = fmaxf(mx, __shfl_xor_sync(0xffffffffu, mx, o));
        float sum = 0.f;
#pragma unroll
        for (int j = 0; j < 8; j++) {
            v[j].x = __expf(v[j].x - mx); v[j].y = __expf(v[j].y - mx);
            v[j].z = __expf(v[j].z - mx); v[j].w = __expf(v[j].w - mx);
            sum += v[j].x + v[j].y + v[j].z + v[j].w;
        }
#pragma unroll
        for (int o = 16; o > 0; o >>= 1)
            sum += __shfl_xor_sync(0xffffffffu, sum, o);
        float inv = 1.0f / sum;
#pragma unroll
        for (int j = 0; j < 8; j++) {
            v[j].x *= inv; v[j].y *= inv; v[j].z *= inv; v[j].w *= inv;
            cs[4 * j + 0] += v[j].x; cs[4 * j + 1] += v[j].y;
            cs[4 * j + 2] += v[j].z; cs[4 * j + 3] += v[j].w;
            *reinterpret_cast<float4*>(&row[lane * 4 + 128 * j]) = v[j];
        }
    }
    float* cbase = colsum + (size_t)(bh * 4 + r) * SS;
#pragma unroll
    for (int j = 0; j < 8; j++)
#pragma unroll
        for (int q = 0; q < 4; q++)
            atomicAdd(&cbase[lane * 4 + 128 * j + q], cs[4 * j + q]);
}

__global__ void init_zero()
{
    int i = blockIdx.x * blockDim.x + threadIdx.x;
    if (i < BB * HH * 4 * SS) g_colsum4[i] = 0.f;
    if (i < BB * CH) g_meanv[i] = 0.f;
}

// meanv: grid (BB, 16), 64-k chunks -> 256 CTAs (was 64; latency-bound)
__global__ void __launch_bounds__(256) meanvec_kernel()
{
    int b = blockIdx.x, kc = blockIdx.y, d = threadIdx.x;
    int k0 = kc * 64;
    float acc0 = 0.f, acc1 = 0.f, acc2 = 0.f, acc3 = 0.f;
    for (int h = 0; h < HH; h++) {
        const float* tv = g_TV + ((size_t)b << 20) + ((size_t)h << 18) + (size_t)k0 * 256;
        const float* cs = g_colsum4 + (size_t)(b * 4 + h) * 4 * SS + k0;
#pragma unroll 4
        for (int k = 0; k < 64; k++) {
            float tvv = tv[(size_t)k * 256 + d];
            acc0 = fmaf(cs[k],          tvv, acc0);
            acc1 = fmaf(cs[SS + k],     tvv, acc1);
            acc2 = fmaf(cs[2 * SS + k], tvv, acc2);
            acc3 = fmaf(cs[3 * SS + k], tvv, acc3);
        }
    }
    const float sc = 1.0f / 1024.0f;
    atomicAdd(&g_meanv[b * CH + 0 * 256 + d], acc0 * sc);
    atomicAdd(&g_meanv[b * CH + 1 * 256 + d], acc1 * sc);
    atomicAdd(&g_meanv[b * CH + 2 * 256 + d], acc2 * sc);
    atomicAdd(&g_meanv[b * CH + 3 * 256 + d], acc3 * sc);
}

__global__ void bvec_kernel(const float* __restrict__ bo,
                            const float* __restrict__ W1,
                            const float* __restrict__ b1)
{
    int j = threadIdx.x;
    float acc = b1[j];
    for (int m = 0; m < 2048; m++) acc = fmaf(bo[m], W1[m * 128 + j], acc);
    g_bvec[j] = acc;
}

__global__ void out_final(float* __restrict__ out)
{
    int b = blockIdx.x, j = threadIdx.x;
    float acc = g_bvec[j];
    const float* mv = g_meanv + b * CH;
    for (int c = 0; c < CH; c++)
        acc = fmaf(mv[c], g_WoW1[c * 128 + j], acc);
    out[b * 128 + j] = acc;
}

// ---------------------------------------------------------------------------
extern "C" void kernel_launch(void* const* d_in, const int* in_sizes, int n_in,
                              void* d_out, int out_size)
{
    const float* query = (const float*)d_in[0];
    const float* key   = (const float*)d_in[1];
    const float* value = (const float*)d_in[2];
    const float* Wq    = (const float*)d_in[3];
    const float* bq    = (const float*)d_in[4];
    const float* Wk    = (const float*)d_in[5];
    const float* bk    = (const float*)d_in[6];
    const float* Wv    = (const float*)d_in[7];
    const float* bv    = (const float*)d_in[8];
    const float* Wo    = (const float*)d_in[9];
    const float* bo    = (const float*)d_in[10];
    const float* W1    = (const float*)d_in[11];
    const float* b1    = (const float*)d_in[12];
    (void)in_sizes; (void)n_in; (void)out_size;

    float* out  = (float*)d_out;
    float* attn = out + (size_t)BB * 128;   // tuple layout: [out, attn]

    void* p;
    cudaGetSymbolAddress(&p, g_TV);      float* TV   = (float*)p;
    cudaGetSymbolAddress(&p, g_colsum4); float* CSUM = (float*)p;
    cudaGetSymbolAddress(&p, g_WoW1);    float* WoW1 = (float*)p;
    __half *Xqh, *Xkh, *Xvh;
    __half *Wqth, *Wqtl, *Wkth, *Wktl, *Wvth, *Wvtl;
    __half *TQh, *TKh;
    cudaGetSymbolAddress(&p, g_Xqh); Xqh = (__half*)p;
    cudaGetSymbolAddress(&p, g_Xkh); Xkh = (__half*)p;
    cudaGetSymbolAddress(&p, g_Xvh); Xvh = (__half*)p;
    cudaGetSymbolAddress(&p, g_Wqth); Wqth = (__half*)p;
    cudaGetSymbolAddress(&p, g_Wqtl); Wqtl = (__half*)p;
    cudaGetSymbolAddress(&p, g_Wkth); Wkth = (__half*)p;
    cudaGetSymbolAddress(&p, g_Wktl); Wktl = (__half*)p;
    cudaGetSymbolAddress(&p, g_Wvth); Wvth = (__half*)p;
    cudaGetSymbolAddress(&p, g_Wvtl); Wvtl = (__half*)p;
    cudaGetSymbolAddress(&p, g_TQh); TQh = (__half*)p;
    cudaGetSymbolAddress(&p, g_TKh); TKh = (__half*)p;

    cudaFuncSetAttribute(mma_nt<2>, cudaFuncAttributeMaxDynamicSharedMemorySize, SMEM_TOTAL);
    cudaFuncSetAttribute(mma_nt<1>, cudaFuncAttributeMaxDynamicSharedMemorySize, SMEM_TOTAL);

    init_zero<<<1024, 256>>>();

    // Convert inputs to fp16 (hi only — lo term dropped in projections)
    convert_kernel<<<(MROWS * QDIM / 4 + 255) / 256, 256>>>(query, Xqh, MROWS * QDIM / 4);
    convert_kernel<<<(MROWS * KDIM / 4 + 255) / 256, 256>>>(key,   Xkh, MROWS * KDIM / 4);
    convert_kernel<<<(MROWS * VDIM / 4 + 255) / 256, 256>>>(value, Xvh, MROWS * VDIM / 4);

    // Transpose + split weights: W[K,1024] -> Wt[1024,K] hi/lo
    tsplit_kernel<<<dim3(32, QDIM / 32), dim3(32, 8)>>>(Wq, Wqth, Wqtl, QDIM, CH);
    tsplit_kernel<<<dim3(32, KDIM / 32), dim3(32, 8)>>>(Wk, Wkth, Wktl, KDIM, CH);
    tsplit_kernel<<<dim3(32, VDIM / 32), dim3(32, 8)>>>(Wv, Wvth, Wvtl, VDIM, CH);

    // Projections (2-term: Xh·(Wh+Wl)): [16384, Kin] @ Wt^T -> [16384, 1024]
    dim3 gp(CH / 128, MROWS / 128, 1);
    mma_nt<2><<<gp, 256, SMEM_TOTAL>>>(Xqh, Wqth, Wqtl, QDIM, QDIM, QDIM,
                                       0, 0, bq, 1, nullptr, TQh);
    mma_nt<2><<<gp, 256, SMEM_TOTAL>>>(Xkh, Wkth, Wktl, KDIM, KDIM, KDIM,
                                       0, 0, bk, 1, nullptr, TKh);
    mma_nt<2><<<gp, 256, SMEM_TOTAL>>>(Xvh, Wvth, Wvtl, VDIM, VDIM, VDIM,
                                       0, 0, bv, 0, TV, nullptr);

    // Small fused tail weights
    gemm_nn_bias<<<dim3(2, 8), 256>>>(Wo, W1, nullptr, WoW1, CH, 128, 2048);
    bvec_kernel<<<1, 128>>>(bo, W1, b1);

    // Scores (1-term pure fp16): per z=(b*4+h), contiguous [1024,256] head block
    dim3 gs(SS / 128, SS / 128, BB * HH);
    mma_nt<1><<<gs, 256, SMEM_TOTAL>>>(TQh, TKh, nullptr, KDIM, KDIM, KDIM,
                                       (long long)SS * KDIM, (long long)SS * SS,
                                       nullptr, 0, attn, nullptr);

    // Softmax in place + stratified column sums
    softmax_colsum<<<256, 256>>>(attn, CSUM);

    // Collapse attended-mean and final projections
    meanvec_kernel<<<dim3(BB, 16), 256>>>();
    out_final<<<BB, 128>>>(out);
}